// round 1
// baseline (speedup 1.0000x reference)
#include <cuda_runtime.h>
#include <cstdint>

#define BN_EPS_F 1e-3f

// ---------------- device scratch (no allocations allowed) ----------------
__device__ float    g_w1f[128*256];       // dequantized folded conv1 weights
__device__ float    g_b1[128];
__device__ unsigned g_w2q[128*9*32];      // int8 bytes: [co][tap][ci], u32-packed along ci
__device__ float    g_b2[128];
__device__ unsigned g_w3q[512*32];        // int8 bytes: [co][ci]
__device__ float    g_b3[512];
__device__ float    g_inv[2];             // 1/(s_w2*25.5), 1/(s_w3*25.5)
__device__ unsigned g_act1[100352*32];    // u8 act, NHWC: [n*3136+p][c], u32-packed
__device__ unsigned g_act2[100352*32];

__device__ __forceinline__ int dp4a_su(int acc, unsigned w_s8, unsigned a_u8){
    int r;
    asm("dp4a.s32.u32 %0, %1, %2, %3;" : "=r"(r) : "r"(w_s8), "r"(a_u8), "r"(acc));
    return r;
}

// ---------------- prep kernels: fold BN, quantize weights/bias ----------------
// Replicate reference rounding exactly: separate rn ops, rintf = round-half-even.

__global__ __launch_bounds__(256) void prep1_kernel(
    const float* __restrict__ w, const float* __restrict__ b,
    const float* __restrict__ g, const float* __restrict__ be,
    const float* __restrict__ m, const float* __restrict__ v)
{
    __shared__ float sc[128];
    __shared__ float red[256];
    int tid = threadIdx.x;
    if (tid < 128) sc[tid] = __fdiv_rn(g[tid], __fsqrt_rn(__fadd_rn(v[tid], BN_EPS_F)));
    __syncthreads();

    float lmax = 0.f;
    for (int i = tid; i < 32768; i += 256) {
        float wf = __fmul_rn(w[i], sc[i >> 8]);
        lmax = fmaxf(lmax, fabsf(wf));
    }
    red[tid] = lmax; __syncthreads();
    for (int s = 128; s > 0; s >>= 1) { if (tid < s) red[tid] = fmaxf(red[tid], red[tid + s]); __syncthreads(); }
    float sw = __fdiv_rn(127.f, fmaxf(red[0], 1e-8f));
    __syncthreads();

    for (int i = tid; i < 32768; i += 256) {
        float wf = __fmul_rn(w[i], sc[i >> 8]);
        g_w1f[i] = __fdiv_rn(rintf(__fmul_rn(wf, sw)), sw);
    }

    float bf = 0.f;
    if (tid < 128) bf = __fadd_rn(__fmul_rn(__fsub_rn(b[tid], m[tid]), sc[tid]), be[tid]);
    red[tid] = fabsf(bf); __syncthreads();
    for (int s = 128; s > 0; s >>= 1) { if (tid < s) red[tid] = fmaxf(red[tid], red[tid + s]); __syncthreads(); }
    float sb = __fdiv_rn(32767.f, fmaxf(red[0], 1e-8f));
    if (tid < 128) g_b1[tid] = __fdiv_rn(rintf(__fmul_rn(bf, sb)), sb);
}

__global__ __launch_bounds__(256) void prep2_kernel(
    const float* __restrict__ w, const float* __restrict__ b,
    const float* __restrict__ g, const float* __restrict__ be,
    const float* __restrict__ m, const float* __restrict__ v)
{
    __shared__ float sc[128];
    __shared__ float red[256];
    int tid = threadIdx.x;
    if (tid < 128) sc[tid] = __fdiv_rn(g[tid], __fsqrt_rn(__fadd_rn(v[tid], BN_EPS_F)));
    __syncthreads();

    float lmax = 0.f;
    for (int i = tid; i < 147456; i += 256) {
        float wf = __fmul_rn(w[i], sc[i / 1152]);
        lmax = fmaxf(lmax, fabsf(wf));
    }
    red[tid] = lmax; __syncthreads();
    for (int s = 128; s > 0; s >>= 1) { if (tid < s) red[tid] = fmaxf(red[tid], red[tid + s]); __syncthreads(); }
    float sw = __fdiv_rn(127.f, fmaxf(red[0], 1e-8f));
    __syncthreads();

    for (int i = tid; i < 147456; i += 256) {
        int o = i / 1152; int rem = i - o * 1152;
        int ci = rem / 9;  int t  = rem - ci * 9;
        float wf = __fmul_rn(w[i], sc[o]);
        int q = (int)rintf(__fmul_rn(wf, sw));
        ((signed char*)g_w2q)[(o * 9 + t) * 128 + ci] = (signed char)q;
    }

    float bf = 0.f;
    if (tid < 128) bf = __fadd_rn(__fmul_rn(__fsub_rn(b[tid], m[tid]), sc[tid]), be[tid]);
    red[tid] = fabsf(bf); __syncthreads();
    for (int s = 128; s > 0; s >>= 1) { if (tid < s) red[tid] = fmaxf(red[tid], red[tid + s]); __syncthreads(); }
    float sb = __fdiv_rn(32767.f, fmaxf(red[0], 1e-8f));
    if (tid < 128) g_b2[tid] = __fdiv_rn(rintf(__fmul_rn(bf, sb)), sb);
    if (tid == 0)  g_inv[0] = __fdiv_rn(1.f, __fmul_rn(sw, 25.5f));
}

__global__ __launch_bounds__(256) void prep3_kernel(
    const float* __restrict__ w, const float* __restrict__ b,
    const float* __restrict__ g, const float* __restrict__ be,
    const float* __restrict__ m, const float* __restrict__ v)
{
    __shared__ float sc[512];
    __shared__ float red[256];
    __shared__ float bfo[512];
    int tid = threadIdx.x;
    for (int o = tid; o < 512; o += 256) sc[o] = __fdiv_rn(g[o], __fsqrt_rn(__fadd_rn(v[o], BN_EPS_F)));
    __syncthreads();

    float lmax = 0.f;
    for (int i = tid; i < 65536; i += 256) {
        float wf = __fmul_rn(w[i], sc[i >> 7]);
        lmax = fmaxf(lmax, fabsf(wf));
    }
    red[tid] = lmax; __syncthreads();
    for (int s = 128; s > 0; s >>= 1) { if (tid < s) red[tid] = fmaxf(red[tid], red[tid + s]); __syncthreads(); }
    float sw = __fdiv_rn(127.f, fmaxf(red[0], 1e-8f));
    __syncthreads();

    for (int i = tid; i < 65536; i += 256) {
        float wf = __fmul_rn(w[i], sc[i >> 7]);
        ((signed char*)g_w3q)[i] = (signed char)(int)rintf(__fmul_rn(wf, sw));
    }

    float lb = 0.f;
    for (int o = tid; o < 512; o += 256) {
        float bf = __fadd_rn(__fmul_rn(__fsub_rn(b[o], m[o]), sc[o]), be[o]);
        bfo[o] = bf;
        lb = fmaxf(lb, fabsf(bf));
    }
    red[tid] = lb; __syncthreads();
    for (int s = 128; s > 0; s >>= 1) { if (tid < s) red[tid] = fmaxf(red[tid], red[tid + s]); __syncthreads(); }
    float sb = __fdiv_rn(32767.f, fmaxf(red[0], 1e-8f));
    for (int o = tid; o < 512; o += 256) g_b3[o] = __fdiv_rn(rintf(__fmul_rn(bfo[o], sb)), sb);
    if (tid == 0) g_inv[1] = __fdiv_rn(1.f, __fmul_rn(sw, 25.5f));
}

// ---------------- conv1: fp32 GEMM 128co x 64px, K=256, epilogue qrelu -> u8 NHWC ----------------
__global__ __launch_bounds__(256) void conv1_kernel(const float* __restrict__ x)
{
    __shared__ float Ws[16 * 136];   // [k][co] padded
    __shared__ float As[16 * 64];    // [k][px]
    int n  = blockIdx.y;
    int p0 = blockIdx.x * 64;
    int tid = threadIdx.x;
    int tr = tid >> 4, tc = tid & 15;
    int co0 = tr * 8, px0 = tc * 4;

    float acc[8][4];
#pragma unroll
    for (int j = 0; j < 8; j++)
#pragma unroll
        for (int q = 0; q < 4; q++) acc[j][q] = 0.f;

    const float* xn = x + ((size_t)n * 256) * 3136 + p0;
    int ar = tid >> 4, ac = (tid & 15) * 4;     // A loader: row k, 4 px
    int wc = tid >> 1, wh = (tid & 1) * 8;      // W loader: co, 8 k

    for (int k0 = 0; k0 < 256; k0 += 16) {
        float4 av  = *(const float4*)(xn + (size_t)(k0 + ar) * 3136 + ac);
        float4 wv0 = *(const float4*)(g_w1f + wc * 256 + k0 + wh);
        float4 wv1 = *(const float4*)(g_w1f + wc * 256 + k0 + wh + 4);
        __syncthreads();
        *(float4*)(As + ar * 64 + ac) = av;
        Ws[(wh + 0) * 136 + wc] = wv0.x; Ws[(wh + 1) * 136 + wc] = wv0.y;
        Ws[(wh + 2) * 136 + wc] = wv0.z; Ws[(wh + 3) * 136 + wc] = wv0.w;
        Ws[(wh + 4) * 136 + wc] = wv1.x; Ws[(wh + 5) * 136 + wc] = wv1.y;
        Ws[(wh + 6) * 136 + wc] = wv1.z; Ws[(wh + 7) * 136 + wc] = wv1.w;
        __syncthreads();
#pragma unroll
        for (int k = 0; k < 16; k++) {
            float4 a4 = *(const float4*)(As + k * 64 + px0);
#pragma unroll
            for (int j = 0; j < 8; j++) {
                float wv = Ws[k * 136 + co0 + j];
                acc[j][0] += wv * a4.x; acc[j][1] += wv * a4.y;
                acc[j][2] += wv * a4.z; acc[j][3] += wv * a4.w;
            }
        }
    }

    float bias[8];
#pragma unroll
    for (int j = 0; j < 8; j++) bias[j] = g_b1[co0 + j];

#pragma unroll
    for (int q = 0; q < 4; q++) {
        unsigned b0 = 0, b1 = 0;
#pragma unroll
        for (int j = 0; j < 8; j++) {
            float vv = acc[j][q] + bias[j];
            vv = fminf(fmaxf(vv, 0.f), 10.f);
            unsigned a = (unsigned)(int)rintf(vv * 25.5f);
            if (j < 4) b0 |= a << (8 * j); else b1 |= a << (8 * (j - 4));
        }
        unsigned idx = ((unsigned)(n * 3136 + p0 + px0 + q)) * 32 + (co0 >> 2);
        g_act1[idx] = b0; g_act1[idx + 1] = b1;
    }
}

// ---------------- conv2: 3x3 int8 dp4a, 8x8 pixel tile, all 128 co ----------------
__global__ __launch_bounds__(256) void conv2_kernel()
{
    __shared__ unsigned Ain[10 * 10 * 32];   // halo tile, XOR-swizzled 16B slots
    __shared__ unsigned Wt[128 * 32];        // per-tap weights
    int n = blockIdx.z, by = blockIdx.y, bx = blockIdx.x;
    int tid = threadIdx.x;
    int tr = tid >> 4, tc = tid & 15;
    int co0 = tr * 8;
    int c8 = tc & 7, r2 = tc >> 3;           // thread pixels: (r2*4+q, c8)

    for (int idx = tid; idx < 3200; idx += 256) {
        int c = idx & 31, pix = idx >> 5;
        int iy = pix / 10, ix = pix - iy * 10;
        int gy = by * 8 + iy - 1, gx = bx * 8 + ix - 1;
        unsigned vv = 0;
        if (gy >= 0 && gy < 56 && gx >= 0 && gx < 56)
            vv = g_act1[((unsigned)(n * 3136 + gy * 56 + gx)) * 32 + c];
        Ain[pix * 32 + (c ^ ((pix & 7) << 2))] = vv;
    }

    int acc[8][4];
#pragma unroll
    for (int j = 0; j < 8; j++)
#pragma unroll
        for (int q = 0; q < 4; q++) acc[j][q] = 0;

    for (int t = 0; t < 9; t++) {
        int dy = t / 3, dx = t - dy * 3;
        __syncthreads();
        for (int idx = tid; idx < 4096; idx += 256) {
            int c = idx & 31, co = idx >> 5;
            Wt[idx] = g_w2q[(co * 9 + t) * 32 + c];
        }
        __syncthreads();

        int pixb[4], swz[4];
#pragma unroll
        for (int q = 0; q < 4; q++) {
            int pix = (r2 * 4 + q + dy) * 10 + (c8 + dx);
            pixb[q] = pix * 32;
            swz[q]  = (pix & 7) << 2;
        }
#pragma unroll
        for (int c4 = 0; c4 < 32; c4 += 4) {
            uint4 a[4];
#pragma unroll
            for (int q = 0; q < 4; q++)
                a[q] = *(const uint4*)&Ain[pixb[q] + (c4 ^ swz[q])];
#pragma unroll
            for (int j = 0; j < 8; j++) {
                uint4 wv = *(const uint4*)&Wt[(co0 + j) * 32 + c4];
#pragma unroll
                for (int q = 0; q < 4; q++) {
                    acc[j][q] = dp4a_su(acc[j][q], wv.x, a[q].x);
                    acc[j][q] = dp4a_su(acc[j][q], wv.y, a[q].y);
                    acc[j][q] = dp4a_su(acc[j][q], wv.z, a[q].z);
                    acc[j][q] = dp4a_su(acc[j][q], wv.w, a[q].w);
                }
            }
        }
    }

    float inv2 = g_inv[0];
    float bias[8];
#pragma unroll
    for (int j = 0; j < 8; j++) bias[j] = g_b2[co0 + j];

#pragma unroll
    for (int q = 0; q < 4; q++) {
        int py = r2 * 4 + q, pxx = c8;
        unsigned b0 = 0, b1 = 0;
#pragma unroll
        for (int j = 0; j < 8; j++) {
            float vv = (float)acc[j][q] * inv2 + bias[j];
            vv = fminf(fmaxf(vv, 0.f), 10.f);
            unsigned a = (unsigned)(int)rintf(vv * 25.5f);
            if (j < 4) b0 |= a << (8 * j); else b1 |= a << (8 * (j - 4));
        }
        unsigned gp = (unsigned)(n * 3136 + (by * 8 + py) * 56 + (bx * 8 + pxx));
        g_act2[gp * 32 + (co0 >> 2)] = b0;
        g_act2[gp * 32 + (co0 >> 2) + 1] = b1;
    }
}

// ---------------- conv3: 1x1 int8 dp4a GEMM, 128co-group x 64px, K=128, fp32 NCHW out ----------------
__global__ __launch_bounds__(256) void conv3_kernel(float* __restrict__ out)
{
    __shared__ unsigned As[64 * 32];
    __shared__ unsigned Wt[128 * 32];
    int n  = blockIdx.z;
    int cg = blockIdx.y;
    int p0 = blockIdx.x * 64;
    int tid = threadIdx.x;
    int tr = tid >> 4, tc = tid & 15;
    int co0 = tr * 8;

    for (int idx = tid; idx < 4096; idx += 256) {
        int c = idx & 31, co = idx >> 5;
        Wt[idx] = g_w3q[(cg * 128 + co) * 32 + c];
    }
    for (int idx = tid; idx < 2048; idx += 256) {
        int c = idx & 31, pix = idx >> 5;
        As[pix * 32 + (c ^ ((pix & 7) << 2))] =
            g_act2[((unsigned)(n * 3136 + p0 + pix)) * 32 + c];
    }
    __syncthreads();

    int acc[8][4];
#pragma unroll
    for (int j = 0; j < 8; j++)
#pragma unroll
        for (int q = 0; q < 4; q++) acc[j][q] = 0;

    int pixb[4], swz[4];
#pragma unroll
    for (int q = 0; q < 4; q++) {
        int pix = tc + 16 * q;                  // strided so LDS phases hit consecutive pixels
        pixb[q] = pix * 32;
        swz[q]  = (pix & 7) << 2;
    }
#pragma unroll
    for (int c4 = 0; c4 < 32; c4 += 4) {
        uint4 a[4];
#pragma unroll
        for (int q = 0; q < 4; q++)
            a[q] = *(const uint4*)&As[pixb[q] + (c4 ^ swz[q])];
#pragma unroll
        for (int j = 0; j < 8; j++) {
            uint4 wv = *(const uint4*)&Wt[(co0 + j) * 32 + c4];
#pragma unroll
            for (int q = 0; q < 4; q++) {
                acc[j][q] = dp4a_su(acc[j][q], wv.x, a[q].x);
                acc[j][q] = dp4a_su(acc[j][q], wv.y, a[q].y);
                acc[j][q] = dp4a_su(acc[j][q], wv.z, a[q].z);
                acc[j][q] = dp4a_su(acc[j][q], wv.w, a[q].w);
            }
        }
    }

    float inv3 = g_inv[1];
#pragma unroll
    for (int j = 0; j < 8; j++) {
        float bj = g_b3[cg * 128 + co0 + j];
        size_t base = ((size_t)n * 512 + cg * 128 + co0 + j) * 3136 + p0;
#pragma unroll
        for (int q = 0; q < 4; q++)
            out[base + tc + 16 * q] = (float)acc[j][q] * inv3 + bj;
    }
}

// ---------------- launch ----------------
extern "C" void kernel_launch(void* const* d_in, const int* in_sizes, int n_in,
                              void* d_out, int out_size)
{
    const float* x   = (const float*)d_in[0];
    const float* w1  = (const float*)d_in[1];
    const float* b1  = (const float*)d_in[2];
    const float* g1  = (const float*)d_in[3];
    const float* be1 = (const float*)d_in[4];
    const float* m1  = (const float*)d_in[5];
    const float* v1  = (const float*)d_in[6];
    const float* w2  = (const float*)d_in[7];
    const float* b2  = (const float*)d_in[8];
    const float* g2  = (const float*)d_in[9];
    const float* be2 = (const float*)d_in[10];
    const float* m2  = (const float*)d_in[11];
    const float* v2  = (const float*)d_in[12];
    const float* w3  = (const float*)d_in[13];
    const float* b3  = (const float*)d_in[14];
    const float* g3  = (const float*)d_in[15];
    const float* be3 = (const float*)d_in[16];
    const float* m3  = (const float*)d_in[17];
    const float* v3  = (const float*)d_in[18];

    prep1_kernel<<<1, 256>>>(w1, b1, g1, be1, m1, v1);
    prep2_kernel<<<1, 256>>>(w2, b2, g2, be2, m2, v2);
    prep3_kernel<<<1, 256>>>(w3, b3, g3, be3, m3, v3);

    conv1_kernel<<<dim3(49, 32), 256>>>(x);
    conv2_kernel<<<dim3(7, 7, 32), 256>>>();
    conv3_kernel<<<dim3(49, 4, 32), 256>>>((float*)d_out);
}

// round 2
// speedup vs baseline: 1.0300x; 1.0300x over previous
#include <cuda_runtime.h>
#include <cstdint>

#define BN_EPS_F 1e-3f

// ---------------- device scratch ----------------
__device__ float    g_w1f[256*128];       // TRANSPOSED folded conv1 weights: [k][co]
__device__ float    g_b1[128];
__device__ unsigned g_w2q[128*9*32];      // int8 bytes: [co][tap][ci], u32-packed along ci
__device__ float    g_b2[128];
__device__ unsigned g_w3q[512*32];        // int8 bytes: [co][ci]
__device__ float    g_b3[512];
__device__ float    g_inv[2];
__device__ unsigned g_act1[100352*32];    // u8 act NHWC [n*3136+p][c/4]
__device__ unsigned g_act2[100352*32];

__device__ __forceinline__ int dp4a_su(int acc, unsigned w_s8, unsigned a_u8){
    int r;
    asm("dp4a.s32.u32 %0, %1, %2, %3;" : "=r"(r) : "r"(w_s8), "r"(a_u8), "r"(acc));
    return r;
}

// ---------------- prep: fold BN, quantize ----------------
__global__ __launch_bounds__(512) void prep1_kernel(
    const float* __restrict__ w, const float* __restrict__ b,
    const float* __restrict__ g, const float* __restrict__ be,
    const float* __restrict__ m, const float* __restrict__ v)
{
    __shared__ float sc[128];
    __shared__ float red[512];
    int tid = threadIdx.x;
    if (tid < 128) sc[tid] = __fdiv_rn(g[tid], __fsqrt_rn(__fadd_rn(v[tid], BN_EPS_F)));
    __syncthreads();

    float lmax = 0.f;
    for (int i = tid; i < 32768; i += 512) {
        float wf = __fmul_rn(w[i], sc[i >> 8]);
        lmax = fmaxf(lmax, fabsf(wf));
    }
    red[tid] = lmax; __syncthreads();
    for (int s = 256; s > 0; s >>= 1) { if (tid < s) red[tid] = fmaxf(red[tid], red[tid + s]); __syncthreads(); }
    float sw = __fdiv_rn(127.f, fmaxf(red[0], 1e-8f));
    __syncthreads();

    for (int i = tid; i < 32768; i += 512) {
        float wf = __fmul_rn(w[i], sc[i >> 8]);
        // transposed store: [k][co]
        g_w1f[(i & 255) * 128 + (i >> 8)] = __fdiv_rn(rintf(__fmul_rn(wf, sw)), sw);
    }

    float bf = 0.f;
    if (tid < 128) bf = __fadd_rn(__fmul_rn(__fsub_rn(b[tid], m[tid]), sc[tid]), be[tid]);
    red[tid] = fabsf(bf); __syncthreads();
    for (int s = 256; s > 0; s >>= 1) { if (tid < s) red[tid] = fmaxf(red[tid], red[tid + s]); __syncthreads(); }
    float sb = __fdiv_rn(32767.f, fmaxf(red[0], 1e-8f));
    if (tid < 128) g_b1[tid] = __fdiv_rn(rintf(__fmul_rn(bf, sb)), sb);
}

__global__ __launch_bounds__(512) void prep2_kernel(
    const float* __restrict__ w, const float* __restrict__ b,
    const float* __restrict__ g, const float* __restrict__ be,
    const float* __restrict__ m, const float* __restrict__ v)
{
    __shared__ float sc[128];
    __shared__ float red[512];
    int tid = threadIdx.x;
    if (tid < 128) sc[tid] = __fdiv_rn(g[tid], __fsqrt_rn(__fadd_rn(v[tid], BN_EPS_F)));
    __syncthreads();

    float lmax = 0.f;
    for (int i = tid; i < 147456; i += 512) {
        float wf = __fmul_rn(w[i], sc[i / 1152]);
        lmax = fmaxf(lmax, fabsf(wf));
    }
    red[tid] = lmax; __syncthreads();
    for (int s = 256; s > 0; s >>= 1) { if (tid < s) red[tid] = fmaxf(red[tid], red[tid + s]); __syncthreads(); }
    float sw = __fdiv_rn(127.f, fmaxf(red[0], 1e-8f));
    __syncthreads();

    for (int i = tid; i < 147456; i += 512) {
        int o = i / 1152; int rem = i - o * 1152;
        int ci = rem / 9;  int t  = rem - ci * 9;
        float wf = __fmul_rn(w[i], sc[o]);
        int q = (int)rintf(__fmul_rn(wf, sw));
        ((signed char*)g_w2q)[(o * 9 + t) * 128 + ci] = (signed char)q;
    }

    float bf = 0.f;
    if (tid < 128) bf = __fadd_rn(__fmul_rn(__fsub_rn(b[tid], m[tid]), sc[tid]), be[tid]);
    red[tid] = fabsf(bf); __syncthreads();
    for (int s = 256; s > 0; s >>= 1) { if (tid < s) red[tid] = fmaxf(red[tid], red[tid + s]); __syncthreads(); }
    float sb = __fdiv_rn(32767.f, fmaxf(red[0], 1e-8f));
    if (tid < 128) g_b2[tid] = __fdiv_rn(rintf(__fmul_rn(bf, sb)), sb);
    if (tid == 0)  g_inv[0] = __fdiv_rn(1.f, __fmul_rn(sw, 25.5f));
}

__global__ __launch_bounds__(512) void prep3_kernel(
    const float* __restrict__ w, const float* __restrict__ b,
    const float* __restrict__ g, const float* __restrict__ be,
    const float* __restrict__ m, const float* __restrict__ v)
{
    __shared__ float sc[512];
    __shared__ float red[512];
    __shared__ float bfo[512];
    int tid = threadIdx.x;
    sc[tid] = __fdiv_rn(g[tid], __fsqrt_rn(__fadd_rn(v[tid], BN_EPS_F)));
    __syncthreads();

    float lmax = 0.f;
    for (int i = tid; i < 65536; i += 512) {
        float wf = __fmul_rn(w[i], sc[i >> 7]);
        lmax = fmaxf(lmax, fabsf(wf));
    }
    red[tid] = lmax; __syncthreads();
    for (int s = 256; s > 0; s >>= 1) { if (tid < s) red[tid] = fmaxf(red[tid], red[tid + s]); __syncthreads(); }
    float sw = __fdiv_rn(127.f, fmaxf(red[0], 1e-8f));
    __syncthreads();

    for (int i = tid; i < 65536; i += 512) {
        float wf = __fmul_rn(w[i], sc[i >> 7]);
        ((signed char*)g_w3q)[i] = (signed char)(int)rintf(__fmul_rn(wf, sw));
    }

    float bf = __fadd_rn(__fmul_rn(__fsub_rn(b[tid], m[tid]), sc[tid]), be[tid]);
    bfo[tid] = bf;
    red[tid] = fabsf(bf); __syncthreads();
    for (int s = 256; s > 0; s >>= 1) { if (tid < s) red[tid] = fmaxf(red[tid], red[tid + s]); __syncthreads(); }
    float sb = __fdiv_rn(32767.f, fmaxf(red[0], 1e-8f));
    g_b3[tid] = __fdiv_rn(rintf(__fmul_rn(bfo[tid], sb)), sb);
    if (tid == 0) g_inv[1] = __fdiv_rn(1.f, __fmul_rn(sw, 25.5f));
}

// ---------------- conv1: fp32 GEMM, 128co x 128px tile, thread 8x8 ----------------
__global__ __launch_bounds__(256) void conv1_kernel(const float* __restrict__ x)
{
    __shared__ float As[16 * 128];
    __shared__ float Ws[16 * 128];
    int n  = blockIdx.y;
    int p0 = blockIdx.x * 128;
    int tid = threadIdx.x;
    int tr = tid >> 4, tc = tid & 15;
    int co0 = tr * 8;
    int pxa = tc * 4, pxb = tc * 4 + 64;

    float acc[8][8];
#pragma unroll
    for (int j = 0; j < 8; j++)
#pragma unroll
        for (int q = 0; q < 8; q++) acc[j][q] = 0.f;

    const float* xn = x + ((size_t)n * 256) * 3136;
    int lr = tid >> 4;                 // k row 0..15
    int lc1 = (tid & 15) * 4;          // col a
    int lc2 = lc1 + 64;                // col b
    int pc1 = min(p0 + lc1, 3132);
    int pc2 = min(p0 + lc2, 3132);

    float4 a1 = *(const float4*)(xn + (size_t)lr * 3136 + pc1);
    float4 a2 = *(const float4*)(xn + (size_t)lr * 3136 + pc2);
    float4 w1 = *(const float4*)(g_w1f + lr * 128 + lc1);
    float4 w2 = *(const float4*)(g_w1f + lr * 128 + lc2);

    for (int k0 = 0; k0 < 256; k0 += 16) {
        __syncthreads();
        *(float4*)(As + lr * 128 + lc1) = a1;
        *(float4*)(As + lr * 128 + lc2) = a2;
        *(float4*)(Ws + lr * 128 + lc1) = w1;
        *(float4*)(Ws + lr * 128 + lc2) = w2;
        __syncthreads();
        if (k0 < 240) {
            a1 = *(const float4*)(xn + (size_t)(k0 + 16 + lr) * 3136 + pc1);
            a2 = *(const float4*)(xn + (size_t)(k0 + 16 + lr) * 3136 + pc2);
            w1 = *(const float4*)(g_w1f + (k0 + 16 + lr) * 128 + lc1);
            w2 = *(const float4*)(g_w1f + (k0 + 16 + lr) * 128 + lc2);
        }
#pragma unroll
        for (int k = 0; k < 16; k++) {
            float4 av0 = *(const float4*)(As + k * 128 + pxa);
            float4 av1 = *(const float4*)(As + k * 128 + pxb);
            float4 wv0 = *(const float4*)(Ws + k * 128 + co0);
            float4 wv1 = *(const float4*)(Ws + k * 128 + co0 + 4);
            float wreg[8] = {wv0.x, wv0.y, wv0.z, wv0.w, wv1.x, wv1.y, wv1.z, wv1.w};
            float areg[8] = {av0.x, av0.y, av0.z, av0.w, av1.x, av1.y, av1.z, av1.w};
#pragma unroll
            for (int j = 0; j < 8; j++)
#pragma unroll
                for (int q = 0; q < 8; q++)
                    acc[j][q] += wreg[j] * areg[q];
        }
    }

    float bias[8];
#pragma unroll
    for (int j = 0; j < 8; j++) bias[j] = g_b1[co0 + j];

#pragma unroll
    for (int q = 0; q < 8; q++) {
        int p = p0 + (q < 4 ? (pxa + q) : (pxb + q - 4));
        if (p >= 3136) continue;
        unsigned b0 = 0, b1 = 0;
#pragma unroll
        for (int j = 0; j < 8; j++) {
            float vv = acc[j][q] + bias[j];
            vv = fminf(fmaxf(vv, 0.f), 10.f);
            unsigned a = (unsigned)(int)rintf(vv * 25.5f);
            if (j < 4) b0 |= a << (8 * j); else b1 |= a << (8 * (j - 4));
        }
        *(uint2*)&g_act1[((unsigned)(n * 3136 + p)) * 32 + tr * 2] = make_uint2(b0, b1);
    }
}

// ---------------- conv2: 3x3 int8 dp4a, 14x8 px tile, 128 co, thread 8co x 7px ----------------
__global__ __launch_bounds__(256) void conv2_kernel()
{
    __shared__ unsigned Ain[16 * 10 * 32];   // halo 16 rows x 10 cols, swizzled 16B slots
    __shared__ unsigned Wt[128 * 32];
    int n = blockIdx.z, by = blockIdx.y, bx = blockIdx.x;
    int tid = threadIdx.x;
    int tr = tid >> 4, tc = tid & 15;
    int co0 = tr * 8;
    int xx = tc & 7, yb = (tc >> 3) * 7;

    for (int idx = tid; idx < 5120; idx += 256) {
        int c = idx & 31, pix = idx >> 5;
        int iy = pix / 10, ix = pix - iy * 10;
        int gy = by * 14 + iy - 1, gx = bx * 8 + ix - 1;
        unsigned vv = 0;
        if (gy >= 0 && gy < 56 && gx >= 0 && gx < 56)
            vv = g_act1[((unsigned)(n * 3136 + gy * 56 + gx)) * 32 + c];
        Ain[pix * 32 + (c ^ ((pix & 7) << 2))] = vv;
    }

    int acc[8][7];
#pragma unroll
    for (int j = 0; j < 8; j++)
#pragma unroll
        for (int q = 0; q < 7; q++) acc[j][q] = 0;

    for (int t = 0; t < 9; t++) {
        int dy = t / 3, dx = t - dy * 3;
        __syncthreads();
        {
            int u = tid;                             // 1024 uint4 / 256 threads
#pragma unroll
            for (int r = 0; r < 4; r++, u += 256) {
                int co = u >> 3, c4 = (u & 7) * 4;
                *(uint4*)&Wt[co * 32 + c4] = *(const uint4*)&g_w2q[(co * 9 + t) * 32 + c4];
            }
        }
        __syncthreads();

        int pixb[7], swz[7];
#pragma unroll
        for (int q = 0; q < 7; q++) {
            int pix = (yb + q + dy) * 10 + (xx + dx);
            pixb[q] = pix * 32;
            swz[q]  = (pix & 7) << 2;
        }
#pragma unroll
        for (int c4 = 0; c4 < 32; c4 += 4) {
            uint4 a[7];
#pragma unroll
            for (int q = 0; q < 7; q++)
                a[q] = *(const uint4*)&Ain[pixb[q] + (c4 ^ swz[q])];
#pragma unroll
            for (int j = 0; j < 8; j++) {
                uint4 wv = *(const uint4*)&Wt[(co0 + j) * 32 + c4];
#pragma unroll
                for (int q = 0; q < 7; q++) {
                    acc[j][q] = dp4a_su(acc[j][q], wv.x, a[q].x);
                    acc[j][q] = dp4a_su(acc[j][q], wv.y, a[q].y);
                    acc[j][q] = dp4a_su(acc[j][q], wv.z, a[q].z);
                    acc[j][q] = dp4a_su(acc[j][q], wv.w, a[q].w);
                }
            }
        }
    }

    float inv2 = g_inv[0];
    float bias[8];
#pragma unroll
    for (int j = 0; j < 8; j++) bias[j] = g_b2[co0 + j];

#pragma unroll
    for (int q = 0; q < 7; q++) {
        int gy = by * 14 + yb + q, gx = bx * 8 + xx;
        unsigned b0 = 0, b1 = 0;
#pragma unroll
        for (int j = 0; j < 8; j++) {
            float vv = (float)acc[j][q] * inv2 + bias[j];
            vv = fminf(fmaxf(vv, 0.f), 10.f);
            unsigned a = (unsigned)(int)rintf(vv * 25.5f);
            if (j < 4) b0 |= a << (8 * j); else b1 |= a << (8 * (j - 4));
        }
        *(uint2*)&g_act2[((unsigned)(n * 3136 + gy * 56 + gx)) * 32 + tr * 2] = make_uint2(b0, b1);
    }
}

// ---------------- conv3: 1x1 int8 dp4a GEMM, 128co x 128px, thread 8x8 ----------------
__global__ __launch_bounds__(256) void conv3_kernel(float* __restrict__ out)
{
    __shared__ unsigned As[128 * 32];
    __shared__ unsigned Wt[128 * 32];
    int n  = blockIdx.z;
    int cg = blockIdx.y;
    int p0 = blockIdx.x * 128;
    int tid = threadIdx.x;
    int tr = tid >> 4, tc = tid & 15;
    int co0 = tr * 8;

    {
        int u = tid;
#pragma unroll
        for (int r = 0; r < 4; r++, u += 256) {
            int co = u >> 3, c4 = (u & 7) * 4;
            *(uint4*)&Wt[co * 32 + c4] = *(const uint4*)&g_w3q[(cg * 128 + co) * 32 + c4];
        }
    }
    for (int idx = tid; idx < 4096; idx += 256) {
        int c = idx & 31, pix = idx >> 5;
        int p = p0 + pix;
        unsigned vv = (p < 3136) ? g_act2[((unsigned)(n * 3136 + p)) * 32 + c] : 0u;
        As[pix * 32 + (c ^ ((pix & 7) << 2))] = vv;
    }
    __syncthreads();

    int acc[8][8];
#pragma unroll
    for (int j = 0; j < 8; j++)
#pragma unroll
        for (int q = 0; q < 8; q++) acc[j][q] = 0;

    int pixb[8], swz[8];
#pragma unroll
    for (int q = 0; q < 8; q++) {
        int pix = tc + 16 * q;
        pixb[q] = pix * 32;
        swz[q]  = (pix & 7) << 2;
    }
#pragma unroll
    for (int c4 = 0; c4 < 32; c4 += 4) {
        uint4 a[8];
#pragma unroll
        for (int q = 0; q < 8; q++)
            a[q] = *(const uint4*)&As[pixb[q] + (c4 ^ swz[q])];
#pragma unroll
        for (int j = 0; j < 8; j++) {
            uint4 wv = *(const uint4*)&Wt[(co0 + j) * 32 + c4];
#pragma unroll
            for (int q = 0; q < 8; q++) {
                acc[j][q] = dp4a_su(acc[j][q], wv.x, a[q].x);
                acc[j][q] = dp4a_su(acc[j][q], wv.y, a[q].y);
                acc[j][q] = dp4a_su(acc[j][q], wv.z, a[q].z);
                acc[j][q] = dp4a_su(acc[j][q], wv.w, a[q].w);
            }
        }
    }

    float inv3 = g_inv[1];
#pragma unroll
    for (int j = 0; j < 8; j++) {
        float bj = g_b3[cg * 128 + co0 + j];
        size_t base = ((size_t)n * 512 + cg * 128 + co0 + j) * 3136;
#pragma unroll
        for (int q = 0; q < 8; q++) {
            int p = p0 + tc + 16 * q;
            if (p < 3136)
                out[base + p] = (float)acc[j][q] * inv3 + bj;
        }
    }
}

// ---------------- launch ----------------
extern "C" void kernel_launch(void* const* d_in, const int* in_sizes, int n_in,
                              void* d_out, int out_size)
{
    const float* x   = (const float*)d_in[0];
    const float* w1  = (const float*)d_in[1];
    const float* b1  = (const float*)d_in[2];
    const float* g1  = (const float*)d_in[3];
    const float* be1 = (const float*)d_in[4];
    const float* m1  = (const float*)d_in[5];
    const float* v1  = (const float*)d_in[6];
    const float* w2  = (const float*)d_in[7];
    const float* b2  = (const float*)d_in[8];
    const float* g2  = (const float*)d_in[9];
    const float* be2 = (const float*)d_in[10];
    const float* m2  = (const float*)d_in[11];
    const float* v2  = (const float*)d_in[12];
    const float* w3  = (const float*)d_in[13];
    const float* b3  = (const float*)d_in[14];
    const float* g3  = (const float*)d_in[15];
    const float* be3 = (const float*)d_in[16];
    const float* m3  = (const float*)d_in[17];
    const float* v3  = (const float*)d_in[18];

    prep1_kernel<<<1, 512>>>(w1, b1, g1, be1, m1, v1);
    prep2_kernel<<<1, 512>>>(w2, b2, g2, be2, m2, v2);
    prep3_kernel<<<1, 512>>>(w3, b3, g3, be3, m3, v3);

    conv1_kernel<<<dim3(25, 32), 256>>>(x);
    conv2_kernel<<<dim3(7, 4, 32), 256>>>();
    conv3_kernel<<<dim3(25, 4, 32), 256>>>((float*)d_out);
}

// round 3
// speedup vs baseline: 1.0326x; 1.0025x over previous
#include <cuda_runtime.h>
#include <cstdint>

#define BN_EPS_F 1e-3f

// ---------------- device scratch ----------------
__device__ float    g_w1f[256*128];       // TRANSPOSED folded conv1 weights: [k][co]
__device__ float    g_b1[128];
__device__ unsigned g_w2q[128*9*32];      // int8 bytes: [co][tap][ci], u32-packed along ci
__device__ float    g_b2[128];
__device__ unsigned g_w3q[512*32];        // int8 bytes: [co][ci]
__device__ float    g_b3[512];
__device__ float    g_inv[2];
__device__ unsigned g_act1[100352*32];    // u8 act NHWC [n*3136+p][c/4]
__device__ unsigned g_act2[100352*32];

__device__ __forceinline__ int dp4a_su(int acc, unsigned w_s8, unsigned a_u8){
    int r;
    asm("dp4a.s32.u32 %0, %1, %2, %3;" : "=r"(r) : "r"(w_s8), "r"(a_u8), "r"(acc));
    return r;
}

// ---------------- prep: fold BN, quantize ----------------
__global__ __launch_bounds__(512) void prep1_kernel(
    const float* __restrict__ w, const float* __restrict__ b,
    const float* __restrict__ g, const float* __restrict__ be,
    const float* __restrict__ m, const float* __restrict__ v)
{
    __shared__ float sc[128];
    __shared__ float red[512];
    int tid = threadIdx.x;
    if (tid < 128) sc[tid] = __fdiv_rn(g[tid], __fsqrt_rn(__fadd_rn(v[tid], BN_EPS_F)));
    __syncthreads();

    float lmax = 0.f;
    for (int i = tid; i < 32768; i += 512) {
        float wf = __fmul_rn(w[i], sc[i >> 8]);
        lmax = fmaxf(lmax, fabsf(wf));
    }
    red[tid] = lmax; __syncthreads();
    for (int s = 256; s > 0; s >>= 1) { if (tid < s) red[tid] = fmaxf(red[tid], red[tid + s]); __syncthreads(); }
    float sw = __fdiv_rn(127.f, fmaxf(red[0], 1e-8f));
    __syncthreads();

    for (int i = tid; i < 32768; i += 512) {
        float wf = __fmul_rn(w[i], sc[i >> 8]);
        // transposed store: [k][co]
        g_w1f[(i & 255) * 128 + (i >> 8)] = __fdiv_rn(rintf(__fmul_rn(wf, sw)), sw);
    }

    float bf = 0.f;
    if (tid < 128) bf = __fadd_rn(__fmul_rn(__fsub_rn(b[tid], m[tid]), sc[tid]), be[tid]);
    red[tid] = fabsf(bf); __syncthreads();
    for (int s = 256; s > 0; s >>= 1) { if (tid < s) red[tid] = fmaxf(red[tid], red[tid + s]); __syncthreads(); }
    float sb = __fdiv_rn(32767.f, fmaxf(red[0], 1e-8f));
    if (tid < 128) g_b1[tid] = __fdiv_rn(rintf(__fmul_rn(bf, sb)), sb);
}

__global__ __launch_bounds__(512) void prep2_kernel(
    const float* __restrict__ w, const float* __restrict__ b,
    const float* __restrict__ g, const float* __restrict__ be,
    const float* __restrict__ m, const float* __restrict__ v)
{
    __shared__ float sc[128];
    __shared__ float red[512];
    int tid = threadIdx.x;
    if (tid < 128) sc[tid] = __fdiv_rn(g[tid], __fsqrt_rn(__fadd_rn(v[tid], BN_EPS_F)));
    __syncthreads();

    float lmax = 0.f;
    for (int i = tid; i < 147456; i += 512) {
        float wf = __fmul_rn(w[i], sc[i / 1152]);
        lmax = fmaxf(lmax, fabsf(wf));
    }
    red[tid] = lmax; __syncthreads();
    for (int s = 256; s > 0; s >>= 1) { if (tid < s) red[tid] = fmaxf(red[tid], red[tid + s]); __syncthreads(); }
    float sw = __fdiv_rn(127.f, fmaxf(red[0], 1e-8f));
    __syncthreads();

    for (int i = tid; i < 147456; i += 512) {
        int o = i / 1152; int rem = i - o * 1152;
        int ci = rem / 9;  int t  = rem - ci * 9;
        float wf = __fmul_rn(w[i], sc[o]);
        int q = (int)rintf(__fmul_rn(wf, sw));
        ((signed char*)g_w2q)[(o * 9 + t) * 128 + ci] = (signed char)q;
    }

    float bf = 0.f;
    if (tid < 128) bf = __fadd_rn(__fmul_rn(__fsub_rn(b[tid], m[tid]), sc[tid]), be[tid]);
    red[tid] = fabsf(bf); __syncthreads();
    for (int s = 256; s > 0; s >>= 1) { if (tid < s) red[tid] = fmaxf(red[tid], red[tid + s]); __syncthreads(); }
    float sb = __fdiv_rn(32767.f, fmaxf(red[0], 1e-8f));
    if (tid < 128) g_b2[tid] = __fdiv_rn(rintf(__fmul_rn(bf, sb)), sb);
    if (tid == 0)  g_inv[0] = __fdiv_rn(1.f, __fmul_rn(sw, 25.5f));
}

__global__ __launch_bounds__(512) void prep3_kernel(
    const float* __restrict__ w, const float* __restrict__ b,
    const float* __restrict__ g, const float* __restrict__ be,
    const float* __restrict__ m, const float* __restrict__ v)
{
    __shared__ float sc[512];
    __shared__ float red[512];
    __shared__ float bfo[512];
    int tid = threadIdx.x;
    sc[tid] = __fdiv_rn(g[tid], __fsqrt_rn(__fadd_rn(v[tid], BN_EPS_F)));
    __syncthreads();

    float lmax = 0.f;
    for (int i = tid; i < 65536; i += 512) {
        float wf = __fmul_rn(w[i], sc[i >> 7]);
        lmax = fmaxf(lmax, fabsf(wf));
    }
    red[tid] = lmax; __syncthreads();
    for (int s = 256; s > 0; s >>= 1) { if (tid < s) red[tid] = fmaxf(red[tid], red[tid + s]); __syncthreads(); }
    float sw = __fdiv_rn(127.f, fmaxf(red[0], 1e-8f));
    __syncthreads();

    for (int i = tid; i < 65536; i += 512) {
        float wf = __fmul_rn(w[i], sc[i >> 7]);
        ((signed char*)g_w3q)[i] = (signed char)(int)rintf(__fmul_rn(wf, sw));
    }

    float bf = __fadd_rn(__fmul_rn(__fsub_rn(b[tid], m[tid]), sc[tid]), be[tid]);
    bfo[tid] = bf;
    red[tid] = fabsf(bf); __syncthreads();
    for (int s = 256; s > 0; s >>= 1) { if (tid < s) red[tid] = fmaxf(red[tid], red[tid + s]); __syncthreads(); }
    float sb = __fdiv_rn(32767.f, fmaxf(red[0], 1e-8f));
    g_b3[tid] = __fdiv_rn(rintf(__fmul_rn(bfo[tid], sb)), sb);
    if (tid == 0) g_inv[1] = __fdiv_rn(1.f, __fmul_rn(sw, 25.5f));
}

// ---------------- conv1: fp32 GEMM, 128co x 128px tile, thread 8x8 ----------------
__global__ __launch_bounds__(256) void conv1_kernel(const float* __restrict__ x)
{
    __shared__ float As[16 * 128];
    __shared__ float Ws[16 * 128];
    int n  = blockIdx.y;
    int p0 = blockIdx.x * 128;
    int tid = threadIdx.x;
    int tr = tid >> 4, tc = tid & 15;
    int co0 = tr * 8;
    int pxa = tc * 4, pxb = tc * 4 + 64;

    float acc[8][8];
#pragma unroll
    for (int j = 0; j < 8; j++)
#pragma unroll
        for (int q = 0; q < 8; q++) acc[j][q] = 0.f;

    const float* xn = x + ((size_t)n * 256) * 3136;
    int lr = tid >> 4;                 // k row 0..15
    int lc1 = (tid & 15) * 4;          // col a
    int lc2 = lc1 + 64;                // col b
    int pc1 = min(p0 + lc1, 3132);
    int pc2 = min(p0 + lc2, 3132);

    float4 a1 = *(const float4*)(xn + (size_t)lr * 3136 + pc1);
    float4 a2 = *(const float4*)(xn + (size_t)lr * 3136 + pc2);
    float4 w1 = *(const float4*)(g_w1f + lr * 128 + lc1);
    float4 w2 = *(const float4*)(g_w1f + lr * 128 + lc2);

    for (int k0 = 0; k0 < 256; k0 += 16) {
        __syncthreads();
        *(float4*)(As + lr * 128 + lc1) = a1;
        *(float4*)(As + lr * 128 + lc2) = a2;
        *(float4*)(Ws + lr * 128 + lc1) = w1;
        *(float4*)(Ws + lr * 128 + lc2) = w2;
        __syncthreads();
        if (k0 < 240) {
            a1 = *(const float4*)(xn + (size_t)(k0 + 16 + lr) * 3136 + pc1);
            a2 = *(const float4*)(xn + (size_t)(k0 + 16 + lr) * 3136 + pc2);
            w1 = *(const float4*)(g_w1f + (k0 + 16 + lr) * 128 + lc1);
            w2 = *(const float4*)(g_w1f + (k0 + 16 + lr) * 128 + lc2);
        }
#pragma unroll
        for (int k = 0; k < 16; k++) {
            float4 av0 = *(const float4*)(As + k * 128 + pxa);
            float4 av1 = *(const float4*)(As + k * 128 + pxb);
            float4 wv0 = *(const float4*)(Ws + k * 128 + co0);
            float4 wv1 = *(const float4*)(Ws + k * 128 + co0 + 4);
            float wreg[8] = {wv0.x, wv0.y, wv0.z, wv0.w, wv1.x, wv1.y, wv1.z, wv1.w};
            float areg[8] = {av0.x, av0.y, av0.z, av0.w, av1.x, av1.y, av1.z, av1.w};
#pragma unroll
            for (int j = 0; j < 8; j++)
#pragma unroll
                for (int q = 0; q < 8; q++)
                    acc[j][q] += wreg[j] * areg[q];
        }
    }

    float bias[8];
#pragma unroll
    for (int j = 0; j < 8; j++) bias[j] = g_b1[co0 + j];

#pragma unroll
    for (int q = 0; q < 8; q++) {
        int p = p0 + (q < 4 ? (pxa + q) : (pxb + q - 4));
        if (p >= 3136) continue;
        unsigned b0 = 0, b1 = 0;
#pragma unroll
        for (int j = 0; j < 8; j++) {
            float vv = acc[j][q] + bias[j];
            vv = fminf(fmaxf(vv, 0.f), 10.f);
            unsigned a = (unsigned)(int)rintf(vv * 25.5f);
            if (j < 4) b0 |= a << (8 * j); else b1 |= a << (8 * (j - 4));
        }
        *(uint2*)&g_act1[((unsigned)(n * 3136 + p)) * 32 + tr * 2] = make_uint2(b0, b1);
    }
}

// ---------------- conv2: 3x3 int8 dp4a, 14x8 px tile, 128 co, thread 8co x 7px ----------------
__global__ __launch_bounds__(256) void conv2_kernel()
{
    __shared__ unsigned Ain[16 * 10 * 32];   // halo 16 rows x 10 cols, swizzled 16B slots
    __shared__ unsigned Wt[128 * 32];
    int n = blockIdx.z, by = blockIdx.y, bx = blockIdx.x;
    int tid = threadIdx.x;
    int tr = tid >> 4, tc = tid & 15;
    int co0 = tr * 8;
    int xx = tc & 7, yb = (tc >> 3) * 7;

    for (int idx = tid; idx < 5120; idx += 256) {
        int c = idx & 31, pix = idx >> 5;
        int iy = pix / 10, ix = pix - iy * 10;
        int gy = by * 14 + iy - 1, gx = bx * 8 + ix - 1;
        unsigned vv = 0;
        if (gy >= 0 && gy < 56 && gx >= 0 && gx < 56)
            vv = g_act1[((unsigned)(n * 3136 + gy * 56 + gx)) * 32 + c];
        Ain[pix * 32 + (c ^ ((pix & 7) << 2))] = vv;
    }

    int acc[8][7];
#pragma unroll
    for (int j = 0; j < 8; j++)
#pragma unroll
        for (int q = 0; q < 7; q++) acc[j][q] = 0;

    for (int t = 0; t < 9; t++) {
        int dy = t / 3, dx = t - dy * 3;
        __syncthreads();
        {
            int u = tid;                             // 1024 uint4 / 256 threads
#pragma unroll
            for (int r = 0; r < 4; r++, u += 256) {
                int co = u >> 3, c4 = (u & 7) * 4;
                *(uint4*)&Wt[co * 32 + c4] = *(const uint4*)&g_w2q[(co * 9 + t) * 32 + c4];
            }
        }
        __syncthreads();

        int pixb[7], swz[7];
#pragma unroll
        for (int q = 0; q < 7; q++) {
            int pix = (yb + q + dy) * 10 + (xx + dx);
            pixb[q] = pix * 32;
            swz[q]  = (pix & 7) << 2;
        }
#pragma unroll
        for (int c4 = 0; c4 < 32; c4 += 4) {
            uint4 a[7];
#pragma unroll
            for (int q = 0; q < 7; q++)
                a[q] = *(const uint4*)&Ain[pixb[q] + (c4 ^ swz[q])];
#pragma unroll
            for (int j = 0; j < 8; j++) {
                uint4 wv = *(const uint4*)&Wt[(co0 + j) * 32 + c4];
#pragma unroll
                for (int q = 0; q < 7; q++) {
                    acc[j][q] = dp4a_su(acc[j][q], wv.x, a[q].x);
                    acc[j][q] = dp4a_su(acc[j][q], wv.y, a[q].y);
                    acc[j][q] = dp4a_su(acc[j][q], wv.z, a[q].z);
                    acc[j][q] = dp4a_su(acc[j][q], wv.w, a[q].w);
                }
            }
        }
    }

    float inv2 = g_inv[0];
    float bias[8];
#pragma unroll
    for (int j = 0; j < 8; j++) bias[j] = g_b2[co0 + j];

#pragma unroll
    for (int q = 0; q < 7; q++) {
        int gy = by * 14 + yb + q, gx = bx * 8 + xx;
        unsigned b0 = 0, b1 = 0;
#pragma unroll
        for (int j = 0; j < 8; j++) {
            float vv = (float)acc[j][q] * inv2 + bias[j];
            vv = fminf(fmaxf(vv, 0.f), 10.f);
            unsigned a = (unsigned)(int)rintf(vv * 25.5f);
            if (j < 4) b0 |= a << (8 * j); else b1 |= a << (8 * (j - 4));
        }
        *(uint2*)&g_act2[((unsigned)(n * 3136 + gy * 56 + gx)) * 32 + tr * 2] = make_uint2(b0, b1);
    }
}

// ---------------- conv3: 1x1 int8 dp4a GEMM, 128co x 128px, thread 8x8 ----------------
__global__ __launch_bounds__(256) void conv3_kernel(float* __restrict__ out)
{
    __shared__ unsigned As[128 * 32];
    __shared__ unsigned Wt[128 * 32];
    int n  = blockIdx.z;
    int cg = blockIdx.y;
    int p0 = blockIdx.x * 128;
    int tid = threadIdx.x;
    int tr = tid >> 4, tc = tid & 15;
    int co0 = tr * 8;

    {
        int u = tid;
#pragma unroll
        for (int r = 0; r < 4; r++, u += 256) {
            int co = u >> 3, c4 = (u & 7) * 4;
            *(uint4*)&Wt[co * 32 + c4] = *(const uint4*)&g_w3q[(cg * 128 + co) * 32 + c4];
        }
    }
    for (int idx = tid; idx < 4096; idx += 256) {
        int c = idx & 31, pix = idx >> 5;
        int p = p0 + pix;
        unsigned vv = (p < 3136) ? g_act2[((unsigned)(n * 3136 + p)) * 32 + c] : 0u;
        As[pix * 32 + (c ^ ((pix & 7) << 2))] = vv;
    }
    __syncthreads();

    int acc[8][8];
#pragma unroll
    for (int j = 0; j < 8; j++)
#pragma unroll
        for (int q = 0; q < 8; q++) acc[j][q] = 0;

    int pixb[8], swz[8];
#pragma unroll
    for (int q = 0; q < 8; q++) {
        int pix = tc + 16 * q;
        pixb[q] = pix * 32;
        swz[q]  = (pix & 7) << 2;
    }
#pragma unroll
    for (int c4 = 0; c4 < 32; c4 += 4) {
        uint4 a[8];
#pragma unroll
        for (int q = 0; q < 8; q++)
            a[q] = *(const uint4*)&As[pixb[q] + (c4 ^ swz[q])];
#pragma unroll
        for (int j = 0; j < 8; j++) {
            uint4 wv = *(const uint4*)&Wt[(co0 + j) * 32 + c4];
#pragma unroll
            for (int q = 0; q < 8; q++) {
                acc[j][q] = dp4a_su(acc[j][q], wv.x, a[q].x);
                acc[j][q] = dp4a_su(acc[j][q], wv.y, a[q].y);
                acc[j][q] = dp4a_su(acc[j][q], wv.z, a[q].z);
                acc[j][q] = dp4a_su(acc[j][q], wv.w, a[q].w);
            }
        }
    }

    float inv3 = g_inv[1];
#pragma unroll
    for (int j = 0; j < 8; j++) {
        float bj = g_b3[cg * 128 + co0 + j];
        size_t base = ((size_t)n * 512 + cg * 128 + co0 + j) * 3136;
#pragma unroll
        for (int q = 0; q < 8; q++) {
            int p = p0 + tc + 16 * q;
            if (p < 3136)
                out[base + p] = (float)acc[j][q] * inv3 + bj;
        }
    }
}

// ---------------- launch ----------------
extern "C" void kernel_launch(void* const* d_in, const int* in_sizes, int n_in,
                              void* d_out, int out_size)
{
    const float* x   = (const float*)d_in[0];
    const float* w1  = (const float*)d_in[1];
    const float* b1  = (const float*)d_in[2];
    const float* g1  = (const float*)d_in[3];
    const float* be1 = (const float*)d_in[4];
    const float* m1  = (const float*)d_in[5];
    const float* v1  = (const float*)d_in[6];
    const float* w2  = (const float*)d_in[7];
    const float* b2  = (const float*)d_in[8];
    const float* g2  = (const float*)d_in[9];
    const float* be2 = (const float*)d_in[10];
    const float* m2  = (const float*)d_in[11];
    const float* v2  = (const float*)d_in[12];
    const float* w3  = (const float*)d_in[13];
    const float* b3  = (const float*)d_in[14];
    const float* g3  = (const float*)d_in[15];
    const float* be3 = (const float*)d_in[16];
    const float* m3  = (const float*)d_in[17];
    const float* v3  = (const float*)d_in[18];

    prep1_kernel<<<1, 512>>>(w1, b1, g1, be1, m1, v1);
    prep2_kernel<<<1, 512>>>(w2, b2, g2, be2, m2, v2);
    prep3_kernel<<<1, 512>>>(w3, b3, g3, be3, m3, v3);

    conv1_kernel<<<dim3(25, 32), 256>>>(x);
    conv2_kernel<<<dim3(7, 4, 32), 256>>>();
    conv3_kernel<<<dim3(25, 4, 32), 256>>>((float*)d_out);
}

// round 6
// speedup vs baseline: 1.0713x; 1.0374x over previous
#include <cuda_runtime.h>
#include <cstdint>

#define BN_EPS_F 1e-3f

__device__ __align__(16) float g_w1f[256*128];
__device__ float g_b1[128];
__device__ __align__(16) unsigned char g_w2q[9*128*128]; // [tap][co][ci] s8
__device__ float g_b2[128];
__device__ int   g_c2[128];
__device__ __align__(16) unsigned char g_w3q[512*128];   // [co][ci] s8
__device__ float g_b3[512];
__device__ int   g_c3[512];
__device__ float g_inv[2];
__device__ __align__(16) unsigned g_act1[100352*32];
__device__ __align__(16) unsigned g_act2[100352*32];

__device__ __forceinline__ uint32_t smem_u32(const void* p){
    uint32_t a;
    asm("{ .reg .u64 t; cvta.to.shared.u64 t, %1; cvt.u32.u64 %0, t; }" : "=r"(a) : "l"(p));
    return a;
}
#define SWZ(o) ((o) ^ (((o) >> 3) & 0x70))

__device__ __forceinline__ void ldsm4(unsigned* r, uint32_t addr){
    asm volatile("ldmatrix.sync.aligned.m8n8.x4.shared.b16 {%0,%1,%2,%3}, [%4];"
        : "=r"(r[0]), "=r"(r[1]), "=r"(r[2]), "=r"(r[3]) : "r"(addr));
}
__device__ __forceinline__ void mma_s8(int* d, const unsigned* a, const unsigned* b){
    asm volatile("mma.sync.aligned.m16n8k32.row.col.s32.s8.s8.s32 "
        "{%0,%1,%2,%3}, {%4,%5,%6,%7}, {%8,%9}, {%0,%1,%2,%3};"
        : "+r"(d[0]), "+r"(d[1]), "+r"(d[2]), "+r"(d[3])
        : "r"(a[0]), "r"(a[1]), "r"(a[2]), "r"(a[3]), "r"(b[0]), "r"(b[1]));
}

// ---------------- prep ----------------
__global__ __launch_bounds__(512) void prep1_kernel(
    const float* __restrict__ w, const float* __restrict__ b,
    const float* __restrict__ g, const float* __restrict__ be,
    const float* __restrict__ m, const float* __restrict__ v)
{
    __shared__ float sc[128]; __shared__ float red[512];
    int tid = threadIdx.x;
    if (tid < 128) sc[tid] = __fdiv_rn(g[tid], __fsqrt_rn(__fadd_rn(v[tid], BN_EPS_F)));
    __syncthreads();
    float lmax = 0.f;
    for (int i = tid; i < 32768; i += 512) lmax = fmaxf(lmax, fabsf(__fmul_rn(w[i], sc[i>>8])));
    red[tid] = lmax; __syncthreads();
    for (int s = 256; s > 0; s >>= 1) { if (tid < s) red[tid] = fmaxf(red[tid], red[tid+s]); __syncthreads(); }
    float sw = __fdiv_rn(127.f, fmaxf(red[0], 1e-8f));
    __syncthreads();
    for (int i = tid; i < 32768; i += 512) {
        float wf = __fmul_rn(w[i], sc[i>>8]);
        g_w1f[(i & 255) * 128 + (i >> 8)] = __fdiv_rn(rintf(__fmul_rn(wf, sw)), sw);
    }
    float bf = 0.f;
    if (tid < 128) bf = __fadd_rn(__fmul_rn(__fsub_rn(b[tid], m[tid]), sc[tid]), be[tid]);
    red[tid] = fabsf(bf); __syncthreads();
    for (int s = 256; s > 0; s >>= 1) { if (tid < s) red[tid] = fmaxf(red[tid], red[tid+s]); __syncthreads(); }
    float sb = __fdiv_rn(32767.f, fmaxf(red[0], 1e-8f));
    if (tid < 128) g_b1[tid] = __fdiv_rn(rintf(__fmul_rn(bf, sb)), sb);
}

__global__ __launch_bounds__(512) void prep2_kernel(
    const float* __restrict__ w, const float* __restrict__ b,
    const float* __restrict__ g, const float* __restrict__ be,
    const float* __restrict__ m, const float* __restrict__ v)
{
    __shared__ float sc[128]; __shared__ float red[512];
    int tid = threadIdx.x;
    if (tid < 128) { sc[tid] = __fdiv_rn(g[tid], __fsqrt_rn(__fadd_rn(v[tid], BN_EPS_F))); g_c2[tid] = 0; }
    __syncthreads();
    float lmax = 0.f;
    for (int i = tid; i < 147456; i += 512) lmax = fmaxf(lmax, fabsf(__fmul_rn(w[i], sc[i/1152])));
    red[tid] = lmax; __syncthreads();
    for (int s = 256; s > 0; s >>= 1) { if (tid < s) red[tid] = fmaxf(red[tid], red[tid+s]); __syncthreads(); }
    float sw = __fdiv_rn(127.f, fmaxf(red[0], 1e-8f));
    __syncthreads();
    for (int i = tid; i < 147456; i += 512) {
        int o = i / 1152, rem = i - o * 1152, ci = rem / 9, t = rem - ci * 9;
        int q = (int)rintf(__fmul_rn(__fmul_rn(w[i], sc[o]), sw));
        ((signed char*)g_w2q)[(t * 128 + o) * 128 + ci] = (signed char)q;
    }
    float bf = 0.f;
    if (tid < 128) bf = __fadd_rn(__fmul_rn(__fsub_rn(b[tid], m[tid]), sc[tid]), be[tid]);
    red[tid] = fabsf(bf); __syncthreads();
    for (int s = 256; s > 0; s >>= 1) { if (tid < s) red[tid] = fmaxf(red[tid], red[tid+s]); __syncthreads(); }
    float sb = __fdiv_rn(32767.f, fmaxf(red[0], 1e-8f));
    if (tid < 128) g_b2[tid] = __fdiv_rn(rintf(__fmul_rn(bf, sb)), sb);
    if (tid == 0)  g_inv[0] = __fdiv_rn(1.f, __fmul_rn(sw, 25.5f));
    int o = tid >> 2, qq = tid & 3, s = 0;
    const signed char* wp = (const signed char*)g_w2q;
    for (int u = qq * 288; u < qq * 288 + 288; u++) {
        int t = u >> 7, ci = u & 127;
        s += wp[(t * 128 + o) * 128 + ci];
    }
    atomicAdd(&g_c2[o], 128 * s);
}

__global__ __launch_bounds__(512) void prep3_kernel(
    const float* __restrict__ w, const float* __restrict__ b,
    const float* __restrict__ g, const float* __restrict__ be,
    const float* __restrict__ m, const float* __restrict__ v)
{
    __shared__ float sc[512]; __shared__ float red[512];
    int tid = threadIdx.x;
    sc[tid] = __fdiv_rn(g[tid], __fsqrt_rn(__fadd_rn(v[tid], BN_EPS_F)));
    __syncthreads();
    float lmax = 0.f;
    for (int i = tid; i < 65536; i += 512) lmax = fmaxf(lmax, fabsf(__fmul_rn(w[i], sc[i>>7])));
    red[tid] = lmax; __syncthreads();
    for (int s = 256; s > 0; s >>= 1) { if (tid < s) red[tid] = fmaxf(red[tid], red[tid+s]); __syncthreads(); }
    float sw = __fdiv_rn(127.f, fmaxf(red[0], 1e-8f));
    __syncthreads();
    for (int i = tid; i < 65536; i += 512)
        ((signed char*)g_w3q)[i] = (signed char)(int)rintf(__fmul_rn(__fmul_rn(w[i], sc[i>>7]), sw));
    float bf = __fadd_rn(__fmul_rn(__fsub_rn(b[tid], m[tid]), sc[tid]), be[tid]);
    red[tid] = fabsf(bf); __syncthreads();
    for (int s = 256; s > 0; s >>= 1) { if (tid < s) red[tid] = fmaxf(red[tid], red[tid+s]); __syncthreads(); }
    float sb = __fdiv_rn(32767.f, fmaxf(red[0], 1e-8f));
    g_b3[tid] = __fdiv_rn(rintf(__fmul_rn(bf, sb)), sb);
    int s = 0;
    const signed char* wp = (const signed char*)g_w3q;
    for (int ci = 0; ci < 128; ci++) s += wp[tid * 128 + ci];
    g_c3[tid] = 128 * s;
    if (tid == 0) g_inv[1] = __fdiv_rn(1.f, __fmul_rn(sw, 25.5f));
}

// ---------------- conv1 (SIMT fp32 GEMM, known good) ----------------
__global__ __launch_bounds__(256) void conv1_kernel(const float* __restrict__ x)
{
    __shared__ float As[16 * 128];
    __shared__ float Ws[16 * 128];
    int n  = blockIdx.y;
    int p0 = blockIdx.x * 128;
    int tid = threadIdx.x;
    int tr = tid >> 4, tc = tid & 15;
    int co0 = tr * 8;
    int pxa = tc * 4, pxb = tc * 4 + 64;

    float acc[8][8];
#pragma unroll
    for (int j = 0; j < 8; j++)
#pragma unroll
        for (int q = 0; q < 8; q++) acc[j][q] = 0.f;

    const float* xn = x + ((size_t)n * 256) * 3136;
    int lr = tid >> 4;
    int lc1 = (tid & 15) * 4, lc2 = lc1 + 64;
    int pc1 = min(p0 + lc1, 3132), pc2 = min(p0 + lc2, 3132);

    float4 a1 = *(const float4*)(xn + (size_t)lr * 3136 + pc1);
    float4 a2 = *(const float4*)(xn + (size_t)lr * 3136 + pc2);
    float4 w1 = *(const float4*)(g_w1f + lr * 128 + lc1);
    float4 w2 = *(const float4*)(g_w1f + lr * 128 + lc2);

    for (int k0 = 0; k0 < 256; k0 += 16) {
        __syncthreads();
        *(float4*)(As + lr * 128 + lc1) = a1;
        *(float4*)(As + lr * 128 + lc2) = a2;
        *(float4*)(Ws + lr * 128 + lc1) = w1;
        *(float4*)(Ws + lr * 128 + lc2) = w2;
        __syncthreads();
        if (k0 < 240) {
            a1 = *(const float4*)(xn + (size_t)(k0 + 16 + lr) * 3136 + pc1);
            a2 = *(const float4*)(xn + (size_t)(k0 + 16 + lr) * 3136 + pc2);
            w1 = *(const float4*)(g_w1f + (k0 + 16 + lr) * 128 + lc1);
            w2 = *(const float4*)(g_w1f + (k0 + 16 + lr) * 128 + lc2);
        }
#pragma unroll
        for (int k = 0; k < 16; k++) {
            float4 av0 = *(const float4*)(As + k * 128 + pxa);
            float4 av1 = *(const float4*)(As + k * 128 + pxb);
            float4 wv0 = *(const float4*)(Ws + k * 128 + co0);
            float4 wv1 = *(const float4*)(Ws + k * 128 + co0 + 4);
            float wreg[8] = {wv0.x, wv0.y, wv0.z, wv0.w, wv1.x, wv1.y, wv1.z, wv1.w};
            float areg[8] = {av0.x, av0.y, av0.z, av0.w, av1.x, av1.y, av1.z, av1.w};
#pragma unroll
            for (int j = 0; j < 8; j++)
#pragma unroll
                for (int q = 0; q < 8; q++)
                    acc[j][q] += wreg[j] * areg[q];
        }
    }

    float bias[8];
#pragma unroll
    for (int j = 0; j < 8; j++) bias[j] = g_b1[co0 + j];
#pragma unroll
    for (int q = 0; q < 8; q++) {
        int p = p0 + (q < 4 ? (pxa + q) : (pxb + q - 4));
        if (p >= 3136) continue;
        unsigned b0 = 0, b1 = 0;
#pragma unroll
        for (int j = 0; j < 8; j++) {
            float vv = acc[j][q] + bias[j];
            vv = fminf(fmaxf(vv, 0.f), 10.f);
            unsigned a = (unsigned)(int)rintf(vv * 25.5f);
            if (j < 4) b0 |= a << (8 * j); else b1 |= a << (8 * (j - 4));
        }
        *(uint2*)&g_act1[((unsigned)(n * 3136 + p)) * 32 + tr * 2] = make_uint2(b0, b1);
    }
}

// ---------------- conv2: mma.sync i8, persistent, 128px x 128co, K=1152 ----------------
__global__ __launch_bounds__(256, 1) void conv2_mma()
{
    extern __shared__ char smem[];
    const uint32_t SM_W = 0, SM_A = 147456, SM_ST = 170496, SM_FB = 186880, SM_CR = 187392;
    uint32_t sb = smem_u32(smem);
    int tid = threadIdx.x, wid = tid >> 5, lane = tid & 31;

    for (int u = tid; u < 9216; u += 256) {             // weights [tap][co][ci] -> swizzled
        uint4 wv = *(const uint4*)(g_w2q + u * 16);
        *(uint4*)(smem + SM_W + SWZ(u * 16)) = wv;
    }
    if (tid < 128) {
        ((float*)(smem + SM_FB))[tid] = g_b2[tid];
        ((int*)(smem + SM_CR))[tid]   = g_c2[tid];
    }
    __syncthreads();
    const float* fbs = (const float*)(smem + SM_FB);
    const int*   crs = (const int*)(smem + SM_CR);
    float inv2 = g_inv[0];

    int wrb = (wid & 3) * 32, wcb = (wid >> 2) * 64;
    int sub = lane >> 3, r8 = lane & 7;
    int row8 = (sub & 1) * 8, kh = (sub >> 1) * 16;      // A lanes: m0..3 = {rLo kLo, rHi kLo, rLo kHi, rHi kHi}
    int rowb = (sub >> 1) * 8, khb = (sub & 1) * 16;     // B lanes: m0..3 = {nLo kLo, nLo kHi, nHi kLo, nHi kHi}

    int yym[2], xxm[2];
#pragma unroll
    for (int mt = 0; mt < 2; mt++) {
        int px = wrb + mt * 16 + row8 + r8;
        yym[mt] = px >> 4; xxm[mt] = px & 15;
    }
    uint32_t wbb[4]; int wxx[4];
#pragma unroll
    for (int bt = 0; bt < 4; bt++) {
        int co = wcb + bt * 16 + rowb + r8;
        wbb[bt] = sb + SM_W + co * 128;
        wxx[bt] = (co & 7) * 16;
    }

    for (int it = 0; it < 7; it++) {
        int t = it * 128 + blockIdx.x;
        int n = t / 28, r = t - n * 28;
        int y0 = (r >> 2) * 8, tx = r & 3;
        int x0 = (tx < 3) ? tx * 16 : 40;

        for (int u = tid; u < 1440; u += 256) {          // halo 10y x 18x rows of 128B
            int hrow = u >> 3, c16 = u & 7;
            int iy = hrow / 18, ix = hrow - iy * 18;
            int gy = y0 + iy - 1, gx = x0 + ix - 1;
            uint4 vv = make_uint4(0x80808080u, 0x80808080u, 0x80808080u, 0x80808080u);
            if (gy >= 0 && gy < 56 && gx >= 0 && gx < 56) {
                vv = *(const uint4*)&g_act1[((unsigned)(n * 3136 + gy * 56 + gx)) * 32 + c16 * 4];
                vv.x ^= 0x80808080u; vv.y ^= 0x80808080u; vv.z ^= 0x80808080u; vv.w ^= 0x80808080u;
            }
            *(uint4*)(smem + SM_A + SWZ(hrow * 128 + c16 * 16)) = vv;
        }
        __syncthreads();

        int acc[2][8][4];
#pragma unroll
        for (int mt = 0; mt < 2; mt++)
#pragma unroll
            for (int nt = 0; nt < 8; nt++)
#pragma unroll
                for (int q = 0; q < 4; q++) acc[mt][nt][q] = 0;

        for (int dy = 0; dy < 3; dy++)
            for (int dx = 0; dx < 3; dx++) {
                uint32_t ab[2]; int axx[2];
#pragma unroll
                for (int mt = 0; mt < 2; mt++) {
                    int hrow = (yym[mt] + dy) * 18 + xxm[mt] + dx;
                    ab[mt] = sb + SM_A + hrow * 128;
                    axx[mt] = (hrow & 7) * 16;
                }
                uint32_t wtap = (dy * 3 + dx) * 16384;
#pragma unroll
                for (int ks = 0; ks < 4; ks++) {
                    unsigned A0[4], A1[4], B[4][4];
                    ldsm4(A0, ab[0] + ((ks * 32 + kh) ^ axx[0]));
                    ldsm4(A1, ab[1] + ((ks * 32 + kh) ^ axx[1]));
#pragma unroll
                    for (int bt = 0; bt < 4; bt++)
                        ldsm4(B[bt], wbb[bt] + wtap + ((ks * 32 + khb) ^ wxx[bt]));
#pragma unroll
                    for (int nt = 0; nt < 8; nt++) {
                        const unsigned* bp = &B[nt >> 1][(nt & 1) * 2];
                        mma_s8(acc[0][nt], A0, bp);
                        mma_s8(acc[1][nt], A1, bp);
                    }
                }
            }

        // epilogue -> swizzled staging (u16 stores)
#pragma unroll
        for (int mt = 0; mt < 2; mt++)
#pragma unroll
            for (int h = 0; h < 2; h++) {
                int px = wrb + mt * 16 + (lane >> 2) + h * 8;
#pragma unroll
                for (int nt = 0; nt < 8; nt++) {
                    int co = wcb + nt * 8 + (lane & 3) * 2;
                    float v0 = (float)(acc[mt][nt][h * 2 + 0] + crs[co]) * inv2 + fbs[co];
                    float v1 = (float)(acc[mt][nt][h * 2 + 1] + crs[co + 1]) * inv2 + fbs[co + 1];
                    v0 = fminf(fmaxf(v0, 0.f), 10.f);
                    v1 = fminf(fmaxf(v1, 0.f), 10.f);
                    unsigned u0 = (unsigned)(int)rintf(v0 * 25.5f);
                    unsigned u1 = (unsigned)(int)rintf(v1 * 25.5f);
                    *(unsigned short*)(smem + SM_ST + px * 128 + (co ^ ((px & 7) * 16))) =
                        (unsigned short)(u0 | (u1 << 8));
                }
            }
        __syncthreads();

        for (int u = tid; u < 1024; u += 256) {
            int px = u >> 3, c16 = u & 7;
            int yy = px >> 4, xx = px & 15;
            unsigned gp = (unsigned)(n * 3136 + (y0 + yy) * 56 + (x0 + xx));
            *(uint4*)&g_act2[gp * 32 + c16 * 4] =
                *(const uint4*)(smem + SM_ST + px * 128 + ((c16 * 16) ^ ((px & 7) * 16)));
        }
        __syncthreads();
    }
}

// ---------------- conv3: mma.sync i8, A=w3 (rows=co), B=act px, fp32 NCHW out ----------------
__global__ __launch_bounds__(256, 1) void conv3_mma(float* __restrict__ out)
{
    extern __shared__ char smem[];
    const uint32_t SM_W = 0, SM_A = 65536, SM_FB = 81920, SM_CR = 83968;
    uint32_t sb = smem_u32(smem);
    int tid = threadIdx.x, wid = tid >> 5, lane = tid & 31;
    int n = blockIdx.y, p0 = blockIdx.x * 128;

    for (int u = tid; u < 4096; u += 256) {              // 512 co rows x 128B
        uint4 wv = *(const uint4*)(g_w3q + u * 16);
        *(uint4*)(smem + SM_W + SWZ(u * 16)) = wv;
    }
    for (int u = tid; u < 1024; u += 256) {              // 128 px rows x 128B
        int pix = u >> 3, c16 = u & 7;
        int p = p0 + pix;
        uint4 vv = make_uint4(0x80808080u, 0x80808080u, 0x80808080u, 0x80808080u);
        if (p < 3136) {
            vv = *(const uint4*)&g_act2[((unsigned)(n * 3136 + p)) * 32 + c16 * 4];
            vv.x ^= 0x80808080u; vv.y ^= 0x80808080u; vv.z ^= 0x80808080u; vv.w ^= 0x80808080u;
        }
        *(uint4*)(smem + SM_A + SWZ(pix * 128 + c16 * 16)) = vv;
    }
    if (tid < 128) {
        ((float4*)(smem + SM_FB))[tid] = *(const float4*)&g_b3[tid * 4];
        ((uint4*)(smem + SM_CR))[tid]  = *(const uint4*)&g_c3[tid * 4];
    }
    __syncthreads();

    const float* fbs = (const float*)(smem + SM_FB);
    const int*   crs = (const int*)(smem + SM_CR);
    float inv3 = g_inv[1];

    int cb0 = wid * 64;
    int sub = lane >> 3, r8 = lane & 7;
    int row8 = (sub & 1) * 8, kh = (sub >> 1) * 16;      // A mapping
    int ntl = (sub >> 1) * 8, kb = (sub & 1) * 16;       // B mapping (pairs contiguous)

    unsigned Af[4][4][4];
#pragma unroll
    for (int amt = 0; amt < 4; amt++) {
        int co = cb0 + amt * 16 + row8 + r8;
        uint32_t base = sb + SM_W + co * 128;
        int xx = (co & 7) * 16;
#pragma unroll
        for (int ks = 0; ks < 4; ks++)
            ldsm4(Af[amt][ks], base + ((ks * 32 + kh) ^ xx));
    }

    for (int pg = 0; pg < 4; pg++) {
        int acc[4][4][4];
#pragma unroll
        for (int a = 0; a < 4; a++)
#pragma unroll
            for (int b = 0; b < 4; b++)
#pragma unroll
                for (int q = 0; q < 4; q++) acc[a][b][q] = 0;

#pragma unroll
        for (int ks = 0; ks < 4; ks++) {
            unsigned Bf[2][4];
#pragma unroll
            for (int bq = 0; bq < 2; bq++) {
                int brow = pg * 32 + bq * 16 + ntl + r8;
                ldsm4(Bf[bq], sb + SM_A + brow * 128 + (((ks * 32 + kb)) ^ ((brow & 7) * 16)));
            }
#pragma unroll
            for (int amt = 0; amt < 4; amt++)
#pragma unroll
                for (int nt = 0; nt < 4; nt++)
                    mma_s8(acc[amt][nt], Af[amt][ks], &Bf[nt >> 1][(nt & 1) * 2]);
        }

#pragma unroll
        for (int amt = 0; amt < 4; amt++)
#pragma unroll
            for (int h = 0; h < 2; h++) {
                int co = cb0 + amt * 16 + (lane >> 2) + h * 8;
                float bj = fbs[co];
                int   cr = crs[co];
                size_t base = ((size_t)n * 512 + co) * 3136;
#pragma unroll
                for (int nt = 0; nt < 4; nt++) {
                    int px = p0 + pg * 32 + nt * 8 + (lane & 3) * 2;
                    if (px < 3136) {
                        float2 o2;
                        o2.x = (float)(acc[amt][nt][h * 2 + 0] + cr) * inv3 + bj;
                        o2.y = (float)(acc[amt][nt][h * 2 + 1] + cr) * inv3 + bj;
                        *(float2*)(out + base + px) = o2;
                    }
                }
            }
    }
}

// ---------------- launch ----------------
extern "C" void kernel_launch(void* const* d_in, const int* in_sizes, int n_in,
                              void* d_out, int out_size)
{
    const float* x   = (const float*)d_in[0];
    const float* w1  = (const float*)d_in[1];
    const float* b1  = (const float*)d_in[2];
    const float* g1  = (const float*)d_in[3];
    const float* be1 = (const float*)d_in[4];
    const float* m1  = (const float*)d_in[5];
    const float* v1  = (const float*)d_in[6];
    const float* w2  = (const float*)d_in[7];
    const float* b2  = (const float*)d_in[8];
    const float* g2  = (const float*)d_in[9];
    const float* be2 = (const float*)d_in[10];
    const float* m2  = (const float*)d_in[11];
    const float* v2  = (const float*)d_in[12];
    const float* w3  = (const float*)d_in[13];
    const float* b3  = (const float*)d_in[14];
    const float* g3  = (const float*)d_in[15];
    const float* be3 = (const float*)d_in[16];
    const float* m3  = (const float*)d_in[17];
    const float* v3  = (const float*)d_in[18];

    cudaFuncSetAttribute(conv2_mma, cudaFuncAttributeMaxDynamicSharedMemorySize, 187904);
    cudaFuncSetAttribute(conv3_mma, cudaFuncAttributeMaxDynamicSharedMemorySize, 86016);

    prep1_kernel<<<1, 512>>>(w1, b1, g1, be1, m1, v1);
    prep2_kernel<<<1, 512>>>(w2, b2, g2, be2, m2, v2);
    prep3_kernel<<<1, 512>>>(w3, b3, g3, be3, m3, v3);

    conv1_kernel<<<dim3(25, 32), 256>>>(x);
    conv2_mma<<<128, 256, 187904>>>();
    conv3_mma<<<dim3(25, 32), 256, 86016>>>((float*)d_out);
}